// round 6
// baseline (speedup 1.0000x reference)
#include <cuda_runtime.h>
#include <cstdint>

#define NB    64
#define NT    100
#define NA    8732
#define VA    4                                  // anchors per thread (NA % 4 == 0)
#define TPB   256
#define APB   (TPB * VA)                         // 1024 anchors per block
#define NBLKM ((NA + APB - 1) / APB)             // 9  main tiles
#define NBLKF ((NA + TPB - 1) / TPB)             // 35 final tiles

// Scratch (static __device__ — allocation is forbidden). Everything here is
// fully (over)written each replay before being read — no init kernel needed.
__device__ float              g_gt_ov [NB * NA];
__device__ int                g_gt_idx[NB * NA];
__device__ unsigned long long g_part  [NBLKM * NB * NT];  // per (tile,b,t) best key
__device__ int                g_ovr   [NB * NA];          // override target id, -1 = none

// key = (iou_bits << 32) | (0xFFFFFFFF - anchor).  iou >= 0 so float bits are
// order-preserving; low word makes ties resolve to the LOWEST anchor index
// (jnp.argmax semantics). max over keys is associative -> deterministic merge.

// Exactly-rounded f32 division, fast path only (no FCHK / no branch).
// Valid: denom is normal & in [4e-4, 2.4], inter in [0, 1.2] — identical
// result sequence to ptxas's div.rn.f32 fast path.
__device__ __forceinline__ float fdiv_rn_fast(float x, float d) {
    float y0;
    asm("rcp.approx.f32 %0, %1;" : "=f"(y0) : "f"(d));
    const float e  = __fmaf_rn(-d, y0, 1.0f);
    const float y1 = __fmaf_rn(y0, e, y0);
    const float q0 = __fmul_rn(x, y1);
    const float r  = __fmaf_rn(-d, q0, x);
    return __fmaf_rn(r, y1, q0);
}

// -------------------------------------------------------------------------
// Kernel 1: IoU pass. grid = (NBLKM, NB), block = 256, VA=4 anchors/thread.
//   Lane-major anchor assignment: lane l owns anchors [warp_a0+4l, +4l+3],
//   so (lane, j) order == anchor order and all tie-breaks stay "lowest".
// -------------------------------------------------------------------------
__global__ __launch_bounds__(TPB) void k_main(const float* __restrict__ targets,
                                              const float* __restrict__ anchors) {
    __shared__ float4             s_box [NT];
    __shared__ float              s_area[NT];
    __shared__ unsigned long long s_key [8 * NT];   // [warp][t]

    const int tid  = threadIdx.x;
    const int wid  = tid >> 5;
    const int lane = tid & 31;
    const int b    = blockIdx.y;

    for (int t = tid; t < NT; t += TPB) {
        const float* tp = targets + ((size_t)b * NT + t) * 5;
        float x1 = tp[0], y1 = tp[1], x2 = tp[2], y2 = tp[3];
        s_box[t]  = make_float4(x1, y1, x2, y2);
        s_area[t] = __fmul_rn(__fsub_rn(x2, x1), __fsub_rn(y2, y1));
    }
    // REQUIRED: warps with warp_a0 >= NA never store keys; their slots must
    // be 0 or the block merge reads garbage (caused R5's illegal access).
    for (int i = tid; i < 8 * NT; i += TPB) s_key[i] = 0ull;
    __syncthreads();

    const int  a0       = (blockIdx.x * TPB + tid) * VA;
    const bool valid    = (a0 < NA);                 // whole group valid (NA%4==0)
    const int  a0c      = valid ? a0 : (NA - VA);    // clamp OOB groups (dup last group)
    const int  warp_a0  = (blockIdx.x * TPB + wid * 32) * VA;
    const bool w_store  = (lane == 0) && (warp_a0 < NA);
    const unsigned inv_base = 0xFFFFFFFFu - (unsigned)warp_a0;

    // anchor point-form for the 4 owned anchors (reference arithmetic exactly)
    float ax1[VA], ay1[VA], ax2[VA], ay2[VA], areaA[VA];
#pragma unroll
    for (int j = 0; j < VA; ++j) {
        const float4 an = reinterpret_cast<const float4*>(anchors)[a0c + j];
        const float hw = __fmul_rn(an.z, 0.5f);
        const float hh = __fmul_rn(an.w, 0.5f);
        ax1[j] = __fsub_rn(an.x, hw);  ay1[j] = __fsub_rn(an.y, hh);
        ax2[j] = __fadd_rn(an.x, hw);  ay2[j] = __fadd_rn(an.y, hh);
        areaA[j] = __fmul_rn(__fsub_rn(ax2[j], ax1[j]), __fsub_rn(ay2[j], ay1[j]));
    }

    float bov[VA];
    int   bt [VA];
#pragma unroll
    for (int j = 0; j < VA; ++j) { bov[j] = -1.0f; bt[j] = 0; }

#pragma unroll 2
    for (int t = 0; t < NT; ++t) {
        const float4 tb   = s_box[t];
        const float areaB = s_area[t];

        float lmax = -1.0f;   // local (4-anchor) max
        int   la   = 0;       // local winner offset 0..3
#pragma unroll
        for (int j = 0; j < VA; ++j) {
            const float tlx = fmaxf(tb.x, ax1[j]);
            const float tly = fmaxf(tb.y, ay1[j]);
            const float brx = fminf(tb.z, ax2[j]);
            const float bry = fminf(tb.w, ay2[j]);
            const float dx  = fmaxf(__fsub_rn(brx, tlx), 0.0f);
            const float dy  = fmaxf(__fsub_rn(bry, tly), 0.0f);
            const float inter = __fmul_rn(dx, dy);
            const float denom = __fsub_rn(__fadd_rn(areaB, areaA[j]), inter);
            const float iou   = fdiv_rn_fast(inter, denom);

            // per-anchor argmax over t (strict > keeps first/lowest t)
            const bool g1 = (iou > bov[j]);
            bov[j] = g1 ? iou : bov[j];
            bt [j] = g1 ? t   : bt[j];

            // local argmax over the 4 anchors (strict > keeps lowest j)
            const bool g2 = (iou > lmax);
            lmax = g2 ? iou : lmax;
            la   = g2 ? j   : la;
        }

        // warp argmax: max iou, ties -> lowest lane (= lowest anchor group).
        // OOB lanes duplicate the last valid group (owned by a lower valid
        // lane), so they can never be elected with a strictly better key.
        const unsigned ib   = __float_as_uint(lmax);
        const unsigned wmax = __reduce_max_sync(0xFFFFFFFFu, ib);
        const unsigned mset = __ballot_sync(0xFFFFFFFFu, ib == wmax);
        const int      wl   = __ffs(mset) - 1;
        const int      wla  = __shfl_sync(0xFFFFFFFFu, la, wl);
        const unsigned long long key =
            ((unsigned long long)wmax << 32) |
            (unsigned long long)(inv_base - (unsigned)(wl * VA + wla));
        if (w_store) s_key[wid * NT + t] = key;       // predicated STS.64
    }

    if (valid) {
        const size_t base = (size_t)b * NA + a0;      // 16B aligned (NA%4==0)
        *reinterpret_cast<float4*>(&g_gt_ov[base]) =
            make_float4(bov[0], bov[1], bov[2], bov[3]);
        *reinterpret_cast<int4*>(&g_gt_idx[base]) =
            make_int4(bt[0], bt[1], bt[2], bt[3]);
        *reinterpret_cast<int4*>(&g_ovr[base]) = make_int4(-1, -1, -1, -1);
    }

    __syncthreads();
    // merge 8 warps -> one key per t for this anchor tile
    if (tid < NT) {
        unsigned long long m = 0ull;
#pragma unroll
        for (int w = 0; w < 8; ++w) {
            unsigned long long v = s_key[w * NT + tid];
            m = (v > m) ? v : m;
        }
        g_part[((size_t)blockIdx.x * NB + b) * NT + tid] = m;
    }
}

// -------------------------------------------------------------------------
// Kernel 2: merge tiles + scatter override. 6400 threads, one per (b,t).
//   Last-t-wins scatter via atomicMax on t (== in-order scatter semantics).
// -------------------------------------------------------------------------
__global__ __launch_bounds__(TPB) void k_merge() {
    const int i = blockIdx.x * TPB + threadIdx.x;
    if (i >= NB * NT) return;
    const int b = i / NT;
    const int t = i - b * NT;

    unsigned long long m = 0ull;
#pragma unroll
    for (int p = 0; p < NBLKM; ++p) {
        unsigned long long v = g_part[((size_t)p * NB + b) * NT + t];
        m = (v > m) ? v : m;
    }
    const int aidx = (int)(0xFFFFFFFFu - (unsigned)(m & 0xFFFFFFFFull));
    atomicMax(&g_ovr[(size_t)b * NA + aidx], t);
}

// -------------------------------------------------------------------------
// Kernel 3: finalize / encode. grid = (NBLKF, NB), block = 256.
// -------------------------------------------------------------------------
__global__ __launch_bounds__(TPB) void k_final(const float* __restrict__ targets,
                                               const float* __restrict__ anchors,
                                               float* __restrict__ out) {
    __shared__ float4 s_box[NT];
    __shared__ float  s_lab[NT];

    const int tid = threadIdx.x;
    const int b   = blockIdx.y;

    for (int t = tid; t < NT; t += TPB) {
        const float* tp = targets + ((size_t)b * NT + t) * 5;
        s_box[t] = make_float4(tp[0], tp[1], tp[2], tp[3]);
        s_lab[t] = tp[4];
    }
    __syncthreads();

    const int a = blockIdx.x * TPB + tid;
    if (a >= NA) return;

    int   gi = g_gt_idx[(size_t)b * NA + a];
    float ov = g_gt_ov [(size_t)b * NA + a];
    const int ovr = g_ovr[(size_t)b * NA + a];
    if (ovr >= 0) { gi = ovr; ov = 1.0f; }

    const float4 m   = s_box[gi];
    const float  lab = s_lab[gi];
    const float4 an  = reinterpret_cast<const float4*>(anchors)[a];

    const float cx = __fmul_rn(__fadd_rn(m.x, m.z), 0.5f);
    const float cy = __fmul_rn(__fadd_rn(m.y, m.w), 0.5f);
    const float w  = __fsub_rn(m.z, m.x);
    const float h  = __fsub_rn(m.w, m.y);

    const float lx = __fdiv_rn(__fsub_rn(cx, an.x), __fmul_rn(0.1f, an.z));
    const float ly = __fdiv_rn(__fsub_rn(cy, an.y), __fmul_rn(0.1f, an.w));
    const float lw = __fdiv_rn(logf(__fdiv_rn(w, an.z)), 0.2f);
    const float lh = __fdiv_rn(logf(__fdiv_rn(h, an.w)), 0.2f);

    const size_t base = (size_t)b * NA + a;
    reinterpret_cast<float4*>(out)[base] = make_float4(lx, ly, lw, lh);

    const float conf = (ov < 0.5f) ? 0.0f : __fadd_rn(lab, 1.0f);
    out[(size_t)NB * NA * 4 + base] = conf;
}

// -------------------------------------------------------------------------
extern "C" void kernel_launch(void* const* d_in, const int* in_sizes, int n_in,
                              void* d_out, int out_size) {
    const float* targets = (const float*)d_in[0];   // [B, T, 5]
    const float* anchors = (const float*)d_in[1];   // [A, 4]
    float* out = (float*)d_out;                     // [B*A*4 loc][B*A conf]

    k_main <<<dim3(NBLKM, NB), TPB>>>(targets, anchors);
    k_merge<<<(NB * NT + TPB - 1) / TPB, TPB>>>();
    k_final<<<dim3(NBLKF, NB), TPB>>>(targets, anchors, out);
}

// round 7
// speedup vs baseline: 1.0097x; 1.0097x over previous
#include <cuda_runtime.h>
#include <cstdint>

#define NB   64
#define NT   100
#define NA   8732
#define TPB  256
#define NBLK ((NA + TPB - 1) / TPB)   // 35 anchor tiles

// Scratch (static __device__ — allocation is forbidden). Everything here is
// fully (over)written each replay before being read — no init kernel needed.
__device__ float              g_gt_ov [NB * NA];
__device__ int                g_gt_idx[NB * NA];
__device__ unsigned long long g_part  [NBLK * NB * NT];  // per (tile,b,t) best key
__device__ int                g_ovr   [NB * NA];         // override target id, -1 = none

// key = (iou_bits << 32) | (0xFFFFFFFF - anchor).  iou >= 0 so float bits are
// order-preserving; low word makes ties resolve to the LOWEST anchor index
// (jnp.argmax semantics). max over keys is associative -> deterministic merge.

// Exactly-rounded f32 division, fast path only (no FCHK / no branch).
// Valid: denom is normal & in [4e-4, 2.4], inter in [0, 1.2] — identical
// result sequence to ptxas's div.rn.f32 fast path.
__device__ __forceinline__ float fdiv_rn_fast(float x, float d) {
    float y0;
    asm("rcp.approx.f32 %0, %1;" : "=f"(y0) : "f"(d));
    const float e  = __fmaf_rn(-d, y0, 1.0f);
    const float y1 = __fmaf_rn(y0, e, y0);
    const float q0 = __fmul_rn(x, y1);
    const float r  = __fmaf_rn(-d, q0, x);
    return __fmaf_rn(r, y1, q0);
}

// -------------------------------------------------------------------------
// Kernel 1: IoU pass. grid = (NBLK, NB), block = 256. Thread owns one anchor.
//   - per-anchor argmax over t in registers (strict >, keeps first/lowest t)
//   - per-target argmax over anchors via DOUBLE REDUX election (no
//     ballot/ffs/shfl): wmax = max(iou_bits); tied lanes submit inv_a;
//     wlow = max(inv_a submissions) = lowest tied anchor.
// -------------------------------------------------------------------------
__global__ __launch_bounds__(TPB) void k_main(const float* __restrict__ targets,
                                              const float* __restrict__ anchors) {
    __shared__ float4             s_box [NT];
    __shared__ float              s_area[NT];
    __shared__ unsigned long long s_key [8 * NT];   // [warp][t]

    const int tid  = threadIdx.x;
    const int wid  = tid >> 5;
    const int lane = tid & 31;
    const int b    = blockIdx.y;

    for (int t = tid; t < NT; t += TPB) {
        const float* tp = targets + ((size_t)b * NT + t) * 5;
        float x1 = tp[0], y1 = tp[1], x2 = tp[2], y2 = tp[3];
        s_box[t]  = make_float4(x1, y1, x2, y2);
        s_area[t] = __fmul_rn(__fsub_rn(x2, x1), __fsub_rn(y2, y1));
    }
    // Warps with warp_a0 >= NA never store keys; their slots must be 0.
    for (int i = tid; i < 8 * NT; i += TPB) s_key[i] = 0ull;
    __syncthreads();

    const int  a       = blockIdx.x * TPB + tid;
    const bool valid   = (a < NA);
    const int  a_ld    = valid ? a : (NA - 1);     // OOB lanes dup last anchor's iou
    const int  warp_a0 = blockIdx.x * TPB + wid * 32;
    const bool w_store = (lane == 0) && (warp_a0 < NA);
    // REAL a here (not clamped): OOB lanes get strictly smaller inv than any
    // valid lane, so a tied OOB lane can never win the low-word election.
    const unsigned inv_a = 0xFFFFFFFFu - (unsigned)a;

    // anchor point-form, replicating reference arithmetic exactly
    const float4 an = reinterpret_cast<const float4*>(anchors)[a_ld];
    const float hw  = __fmul_rn(an.z, 0.5f);
    const float hh  = __fmul_rn(an.w, 0.5f);
    const float ax1 = __fsub_rn(an.x, hw), ay1 = __fsub_rn(an.y, hh);
    const float ax2 = __fadd_rn(an.x, hw), ay2 = __fadd_rn(an.y, hh);
    const float areaA = __fmul_rn(__fsub_rn(ax2, ax1), __fsub_rn(ay2, ay1));

    float best_ov = -1.0f;
    int   best_t  = 0;

#pragma unroll 4
    for (int t = 0; t < NT; ++t) {
        const float4 tb   = s_box[t];
        const float areaB = s_area[t];
        const float tlx = fmaxf(tb.x, ax1);
        const float tly = fmaxf(tb.y, ay1);
        const float brx = fminf(tb.z, ax2);
        const float bry = fminf(tb.w, ay2);
        const float dx  = fmaxf(__fsub_rn(brx, tlx), 0.0f);
        const float dy  = fmaxf(__fsub_rn(bry, tly), 0.0f);
        const float inter = __fmul_rn(dx, dy);
        const float denom = __fsub_rn(__fadd_rn(areaB, areaA), inter);
        const float iou   = fdiv_rn_fast(inter, denom);

        // per-anchor argmax over t (strict > keeps first/lowest t)
        const bool gt = (iou > best_ov);
        best_ov = gt ? iou : best_ov;
        best_t  = gt ? t   : best_t;

        // per-target warp argmax: double REDUX, no ballot/ffs/shfl
        const unsigned ib   = __float_as_uint(iou);
        const unsigned wmax = __reduce_max_sync(0xFFFFFFFFu, ib);
        const unsigned cand = (ib == wmax) ? inv_a : 0u;
        const unsigned wlow = __reduce_max_sync(0xFFFFFFFFu, cand);
        if (w_store)
            s_key[wid * NT + t] =
                ((unsigned long long)wmax << 32) | (unsigned long long)wlow;
    }

    if (valid) {
        g_gt_ov [(size_t)b * NA + a] = best_ov;
        g_gt_idx[(size_t)b * NA + a] = best_t;
        g_ovr   [(size_t)b * NA + a] = -1;            // cleared for k_merge scatter
    }

    __syncthreads();
    // merge 8 warps -> one key per t for this anchor tile
    if (tid < NT) {
        unsigned long long m = 0ull;
#pragma unroll
        for (int w = 0; w < 8; ++w) {
            unsigned long long v = s_key[w * NT + tid];
            m = (v > m) ? v : m;
        }
        g_part[((size_t)blockIdx.x * NB + b) * NT + tid] = m;
    }
}

// -------------------------------------------------------------------------
// Kernel 2: merge tiles + scatter override. 6400 threads, one per (b,t).
//   Last-t-wins scatter via atomicMax on t (== in-order scatter semantics).
// -------------------------------------------------------------------------
__global__ __launch_bounds__(TPB) void k_merge() {
    const int i = blockIdx.x * TPB + threadIdx.x;
    if (i >= NB * NT) return;
    const int b = i / NT;
    const int t = i - b * NT;

    unsigned long long m = 0ull;
#pragma unroll
    for (int p = 0; p < NBLK; ++p) {
        unsigned long long v = g_part[((size_t)p * NB + b) * NT + t];
        m = (v > m) ? v : m;
    }
    const int aidx = (int)(0xFFFFFFFFu - (unsigned)(m & 0xFFFFFFFFull));
    atomicMax(&g_ovr[(size_t)b * NA + aidx], t);
}

// -------------------------------------------------------------------------
// Kernel 3: finalize / encode. grid = (NBLK, NB), block = 256.
//   Output-only math: fast log/div are fine (1e-6 err vs 1e-3 tolerance);
//   all argmax/threshold-relevant values came from the exact pass.
// -------------------------------------------------------------------------
__global__ __launch_bounds__(TPB) void k_final(const float* __restrict__ targets,
                                               const float* __restrict__ anchors,
                                               float* __restrict__ out) {
    __shared__ float4 s_box[NT];
    __shared__ float  s_lab[NT];

    const int tid = threadIdx.x;
    const int b   = blockIdx.y;

    for (int t = tid; t < NT; t += TPB) {
        const float* tp = targets + ((size_t)b * NT + t) * 5;
        s_box[t] = make_float4(tp[0], tp[1], tp[2], tp[3]);
        s_lab[t] = tp[4];
    }
    __syncthreads();

    const int a = blockIdx.x * TPB + tid;
    if (a >= NA) return;

    int   gi = g_gt_idx[(size_t)b * NA + a];
    float ov = g_gt_ov [(size_t)b * NA + a];
    const int ovr = g_ovr[(size_t)b * NA + a];
    if (ovr >= 0) { gi = ovr; ov = 1.0f; }

    const float4 m   = s_box[gi];
    const float  lab = s_lab[gi];
    const float4 an  = reinterpret_cast<const float4*>(anchors)[a];

    const float cx = (m.x + m.z) * 0.5f;
    const float cy = (m.y + m.w) * 0.5f;
    const float w  = m.z - m.x;
    const float h  = m.w - m.y;

    const float lx = __fdividef(cx - an.x, 0.1f * an.z);
    const float ly = __fdividef(cy - an.y, 0.1f * an.w);
    const float lw = __logf(__fdividef(w, an.z)) * 5.0f;
    const float lh = __logf(__fdividef(h, an.w)) * 5.0f;

    const size_t base = (size_t)b * NA + a;
    reinterpret_cast<float4*>(out)[base] = make_float4(lx, ly, lw, lh);

    const float conf = (ov < 0.5f) ? 0.0f : (lab + 1.0f);
    out[(size_t)NB * NA * 4 + base] = conf;
}

// -------------------------------------------------------------------------
extern "C" void kernel_launch(void* const* d_in, const int* in_sizes, int n_in,
                              void* d_out, int out_size) {
    const float* targets = (const float*)d_in[0];   // [B, T, 5]
    const float* anchors = (const float*)d_in[1];   // [A, 4]
    float* out = (float*)d_out;                     // [B*A*4 loc][B*A conf]

    k_main <<<dim3(NBLK, NB), TPB>>>(targets, anchors);
    k_merge<<<(NB * NT + TPB - 1) / TPB, TPB>>>();
    k_final<<<dim3(NBLK, NB), TPB>>>(targets, anchors, out);
}